// round 6
// baseline (speedup 1.0000x reference)
#include <cuda_runtime.h>
#include <cstdint>

// Problem dims (fixed by the dataset)
#define M_DIM 8192
#define N_DIM 11008
#define K_DIM 4096

#define BM 128
#define BN 128
#define BK 128           // int8 K bytes per stage
#define STAGES 3
#define NKIT (K_DIM / BK)   // 32
#define SROW 144         // padded bytes per smem row (128 + 16) -> conflict-free ldmatrix

#define MAT_BYTES (BM * SROW)              // 18432
#define STAGE_BYTES (3 * MAT_BYTES)        // 55296 (A_hi, A_lo, B)
#define SMEM_BYTES (STAGES * STAGE_BYTES)  // 165888

#define NTHREADS 512     // 16 warps, 4x4 grid of 32x32 warp tiles

#define QS (8.0f / 127.0f)   // hi quantization step

// int8 scratch (static device globals: allocation-free per the harness rules)
__device__ int8_t g_XHI[(size_t)M_DIM * K_DIM];   // 33.5 MB
__device__ int8_t g_XLO[(size_t)M_DIM * K_DIM];   // 33.5 MB
__device__ int8_t g_W8 [(size_t)N_DIM * K_DIM];   // 45 MB

// ---------------------------------------------------------------------------
// Pre-pass conversions
// ---------------------------------------------------------------------------
// x -> (hi, lo) int8 pair:  x ~= QS*hi + (QS/127)*lo
__global__ void cvt_x_kernel(const float* __restrict__ x) {
    size_t i = (size_t)blockIdx.x * blockDim.x + threadIdx.x;
    const size_t n4 = (size_t)M_DIM * K_DIM / 4;
    if (i >= n4) return;
    float4 v = reinterpret_cast<const float4*>(x)[i];
    float vv[4] = {v.x, v.y, v.z, v.w};
    char hi[4], lo[4];
#pragma unroll
    for (int k = 0; k < 4; k++) {
        float q = vv[k] * (127.0f / 8.0f);
        q = fminf(fmaxf(q, -127.0f), 127.0f);
        int h = __float2int_rn(q);
        float r = vv[k] - (float)h * QS;
        float ql = r * (127.0f * 127.0f / 8.0f);
        ql = fminf(fmaxf(ql, -127.0f), 127.0f);
        int l = __float2int_rn(ql);
        hi[k] = (char)h;
        lo[k] = (char)l;
    }
    *reinterpret_cast<char4*>(&g_XHI[4 * i]) = make_char4(hi[0], hi[1], hi[2], hi[3]);
    *reinterpret_cast<char4*>(&g_XLO[4 * i]) = make_char4(lo[0], lo[1], lo[2], lo[3]);
}

// Weights arrive as int32 (harness promotes int8 -> int32); pack back to int8.
__global__ void cvt_w_kernel(const int* __restrict__ w) {
    size_t i = (size_t)blockIdx.x * blockDim.x + threadIdx.x;
    const size_t n4 = (size_t)N_DIM * K_DIM / 4;
    if (i >= n4) return;
    int4 v = reinterpret_cast<const int4*>(w)[i];
    *reinterpret_cast<char4*>(&g_W8[4 * i]) =
        make_char4((char)v.x, (char)v.y, (char)v.z, (char)v.w);
}

// ---------------------------------------------------------------------------
// PTX helpers
// ---------------------------------------------------------------------------
__device__ __forceinline__ uint32_t smem_u32(const void* p) {
    return (uint32_t)__cvta_generic_to_shared(p);
}

__device__ __forceinline__ void cp_async16(uint32_t dst, const void* src) {
    asm volatile("cp.async.cg.shared.global [%0], [%1], 16;\n" :: "r"(dst), "l"(src));
}
__device__ __forceinline__ void cp_commit() {
    asm volatile("cp.async.commit_group;\n" ::);
}
template <int Ngroups>
__device__ __forceinline__ void cp_wait() {
    asm volatile("cp.async.wait_group %0;\n" :: "n"(Ngroups));
}

__device__ __forceinline__ void ldsm_x4(uint32_t& r0, uint32_t& r1, uint32_t& r2, uint32_t& r3,
                                        uint32_t addr) {
    asm volatile("ldmatrix.sync.aligned.m8n8.x4.shared.b16 {%0,%1,%2,%3}, [%4];\n"
                 : "=r"(r0), "=r"(r1), "=r"(r2), "=r"(r3) : "r"(addr));
}

// s8 x s8 -> s32, m16n8k32
__device__ __forceinline__ void imma16832(int& c0, int& c1, int& c2, int& c3,
                                          uint32_t a0, uint32_t a1, uint32_t a2, uint32_t a3,
                                          uint32_t b0, uint32_t b1) {
    asm volatile(
        "mma.sync.aligned.m16n8k32.row.col.s32.s8.s8.s32 "
        "{%0,%1,%2,%3}, {%4,%5,%6,%7}, {%8,%9}, {%0,%1,%2,%3};\n"
        : "+r"(c0), "+r"(c1), "+r"(c2), "+r"(c3)
        : "r"(a0), "r"(a1), "r"(a2), "r"(a3), "r"(b0), "r"(b1));
}

// ---------------------------------------------------------------------------
// GEMM: out[M,N] = ws*(QS*(XHI@W8^T) + (QS/127)*(XLO@W8^T)) + bias[N]
// 16 warps (4x4 grid of 32x32 warp tiles), dual int32 accumulators,
// 3-stage cp.async pipeline, BK=128 int8, 1 CTA/SM.
// ---------------------------------------------------------------------------
__global__ void __launch_bounds__(NTHREADS, 1)
gemm_kernel(float* __restrict__ out, const float* __restrict__ scale_p,
            const float* __restrict__ bias) {
    extern __shared__ __align__(16) int8_t smem[];

    const int tid  = threadIdx.x;
    const int lane = tid & 31;
    const int wid  = tid >> 5;   // 0..15
    const int wm   = wid >> 2;   // 0..3  (32-row band)
    const int wn   = wid & 3;    // 0..3  (32-col band)

    // Supertile swizzle for L2 reuse: n-groups of 16, m fastest within group.
    const int MB = M_DIM / BM;   // 64
    const int NB = N_DIM / BN;   // 86
    const int GN = 16;
    int bid   = blockIdx.x;
    int group = bid / (MB * GN);
    int rem   = bid % (MB * GN);
    int n0    = group * GN;
    int width = (NB - n0 < GN) ? (NB - n0) : GN;
    int bm    = rem / width;
    int bn    = n0 + rem % width;

    const int8_t* gAh = g_XHI + (size_t)bm * BM * K_DIM;
    const int8_t* gAl = g_XLO + (size_t)bm * BM * K_DIM;
    const int8_t* gB  = g_W8  + (size_t)bn * BN * K_DIM;

    int acch[2][4][4], accl[2][4][4];
#pragma unroll
    for (int i = 0; i < 2; i++)
#pragma unroll
        for (int j = 0; j < 4; j++)
#pragma unroll
            for (int r = 0; r < 4; r++) { acch[i][j][r] = 0; accl[i][j][r] = 0; }

    // Stage loader: 3 matrices x 128 rows x 128 B = 3072 16B chunks; 6/thread.
    auto load_stage = [&](int s, int it) {
        int8_t* base = smem + s * STAGE_BYTES;
#pragma unroll
        for (int i = 0; i < 6; i++) {
            int c   = tid + (i & 1) * NTHREADS;  // 0..1023
            int row = c >> 3;
            int col = (c & 7) * 16;
            const int8_t* g = (i < 2) ? gAh : (i < 4) ? gAl : gB;
            int moff = (i >> 1) * MAT_BYTES;
            cp_async16(smem_u32(base + moff + row * SROW + col),
                       g + (size_t)row * K_DIM + it * BK + col);
        }
    };

    auto compute = [&](int s) {
        const int8_t* sAh = smem + s * STAGE_BYTES;
        const int8_t* sAl = sAh + MAT_BYTES;
        const int8_t* sB  = sAh + 2 * MAT_BYTES;
#pragma unroll
        for (int kc = 0; kc < 4; kc++) {
            uint32_t ah[2][4], al[2][4], bf[2][4];
            // A fragments (m16k32): rows (lane&15), byte halves via lane>>4
            int arow = (lane & 15);
            int acol = kc * 32 + (lane >> 4) * 16;
#pragma unroll
            for (int i = 0; i < 2; i++) {
                int r = wm * 32 + i * 16 + arow;
                ldsm_x4(ah[i][0], ah[i][1], ah[i][2], ah[i][3],
                        smem_u32(sAh + r * SROW + acol));
                ldsm_x4(al[i][0], al[i][1], al[i][2], al[i][3],
                        smem_u32(sAl + r * SROW + acol));
            }
            // B fragments: x4 covers two n8-tiles (k32 each)
            int brow_in = ((lane >> 4) & 1) * 8 + (lane & 7);
            int bcol    = kc * 32 + ((lane >> 3) & 1) * 16;
#pragma unroll
            for (int jp = 0; jp < 2; jp++) {
                int r = wn * 32 + jp * 16 + brow_in;
                ldsm_x4(bf[jp][0], bf[jp][1], bf[jp][2], bf[jp][3],
                        smem_u32(sB + r * SROW + bcol));
            }
#pragma unroll
            for (int i = 0; i < 2; i++)
#pragma unroll
                for (int j = 0; j < 4; j++) {
                    int jp = j >> 1, sel = j & 1;
                    uint32_t b0 = bf[jp][2 * sel], b1 = bf[jp][2 * sel + 1];
                    imma16832(acch[i][j][0], acch[i][j][1], acch[i][j][2], acch[i][j][3],
                              ah[i][0], ah[i][1], ah[i][2], ah[i][3], b0, b1);
                    imma16832(accl[i][j][0], accl[i][j][1], accl[i][j][2], accl[i][j][3],
                              al[i][0], al[i][1], al[i][2], al[i][3], b0, b1);
                }
        }
    };

    // Prologue: fill first 2 stages
    load_stage(0, 0);
    cp_commit();
    load_stage(1, 1);
    cp_commit();

    int slot = 0;
#pragma unroll 1
    for (int it = 0; it < NKIT; it++) {
        cp_wait<1>();       // stage 'it' loads complete (this thread)
        __syncthreads();    // complete CTA-wide; also protects slot reuse below
        int nslot = slot + 2;
        if (nslot >= STAGES) nslot -= STAGES;
        if (it + 2 < NKIT) load_stage(nslot, it + 2);
        cp_commit();        // uniform group accounting (possibly empty)
        compute(slot);
        if (++slot == STAGES) slot = 0;
    }

    // Epilogue: out = c1*acc_hi + c2*acc_lo + bias   (c = ws * step)
    const float ws = __ldg(scale_p);
    const float c1 = ws * QS;
    const float c2 = ws * (QS / 127.0f);
    const int m_base = bm * BM + wm * 32 + (lane >> 2);
    const int n_base = bn * BN + wn * 32 + (lane & 3) * 2;
#pragma unroll
    for (int i = 0; i < 2; i++) {
#pragma unroll
        for (int j = 0; j < 4; j++) {
            int m = m_base + i * 16;
            int n = n_base + j * 8;
            float2 bv = *reinterpret_cast<const float2*>(&bias[n]);
            float2 r0, r1;
            r0.x = c1 * (float)acch[i][j][0] + c2 * (float)accl[i][j][0] + bv.x;
            r0.y = c1 * (float)acch[i][j][1] + c2 * (float)accl[i][j][1] + bv.y;
            r1.x = c1 * (float)acch[i][j][2] + c2 * (float)accl[i][j][2] + bv.x;
            r1.y = c1 * (float)acch[i][j][3] + c2 * (float)accl[i][j][3] + bv.y;
            *reinterpret_cast<float2*>(&out[(size_t)m * N_DIM + n])       = r0;
            *reinterpret_cast<float2*>(&out[(size_t)(m + 8) * N_DIM + n]) = r1;
        }
    }
}

// ---------------------------------------------------------------------------
// Entry point (graph-capturable: kernel launches only)
// ---------------------------------------------------------------------------
extern "C" void kernel_launch(void* const* d_in, const int* in_sizes, int n_in,
                              void* d_out, int out_size) {
    const float* x     = (const float*)d_in[0];
    const int*   w     = (const int*)d_in[1];    // int8 promoted to int32 by harness
    const float* scale = (const float*)d_in[2];
    const float* bias  = (const float*)d_in[3];
    float*       out   = (float*)d_out;

    cudaFuncSetAttribute(gemm_kernel,
                         cudaFuncAttributeMaxDynamicSharedMemorySize, SMEM_BYTES);

    const size_t nx4 = (size_t)M_DIM * K_DIM / 4;
    cvt_x_kernel<<<(unsigned)((nx4 + 255) / 256), 256>>>(x);
    const size_t nw4 = (size_t)N_DIM * K_DIM / 4;
    cvt_w_kernel<<<(unsigned)((nw4 + 255) / 256), 256>>>(w);

    const int grid = (M_DIM / BM) * (N_DIM / BN);  // 5504
    gemm_kernel<<<grid, NTHREADS, SMEM_BYTES>>>(out, scale, bias);
}

// round 7
// speedup vs baseline: 4.4614x; 4.4614x over previous
#include <cuda_runtime.h>
#include <cuda_fp16.h>
#include <cstdint>

// Problem dims (fixed by the dataset)
#define M_DIM 8192
#define N_DIM 11008
#define K_DIM 4096

#define BM 128
#define BN 128
#define BK 64            // fp16 K elements per stage
#define STAGES 3
#define NKIT (K_DIM / BK)  // 64
#define SSTRIDE 72       // halves per smem row (64 + 8 pad) -> conflict-free ldmatrix

#define STAGE_HALVES (2 * BM * SSTRIDE)          // A + B per stage = 18432 halves
#define A_OFF 0
#define B_OFF (BM * SSTRIDE)                     // 9216 halves
#define SMEM_BYTES (STAGES * STAGE_HALVES * 2)   // 110592 B = 108 KB

// fp16 scratch (static device globals: allocation-free per the harness rules)
__device__ __half g_XH[(size_t)M_DIM * K_DIM];   // 67 MB
__device__ __half g_WH[(size_t)N_DIM * K_DIM];   // 90 MB

// ---------------------------------------------------------------------------
// Pre-pass conversions
// ---------------------------------------------------------------------------
__global__ void cvt_x_kernel(const float* __restrict__ x) {
    size_t i = (size_t)blockIdx.x * blockDim.x + threadIdx.x;
    const size_t n4 = (size_t)M_DIM * K_DIM / 4;
    if (i < n4) {
        float4 v = reinterpret_cast<const float4*>(x)[i];
        __half2* o = reinterpret_cast<__half2*>(g_XH);
        o[2 * i]     = __floats2half2_rn(v.x, v.y);
        o[2 * i + 1] = __floats2half2_rn(v.z, v.w);
    }
}

// Weights arrive as int32 (harness promotes int8 -> int32).
__global__ void cvt_w_kernel(const int* __restrict__ w) {
    size_t i = (size_t)blockIdx.x * blockDim.x + threadIdx.x;
    const size_t n4 = (size_t)N_DIM * K_DIM / 4;
    if (i < n4) {
        int4 v = reinterpret_cast<const int4*>(w)[i];
        __half2* o = reinterpret_cast<__half2*>(g_WH);
        o[2 * i]     = __halves2half2(__int2half_rn(v.x), __int2half_rn(v.y));
        o[2 * i + 1] = __halves2half2(__int2half_rn(v.z), __int2half_rn(v.w));
    }
}

// No-op launch-index padding so ncu's "-s 5 -c 1" window lands on gemm_kernel.
__global__ void noop_kernel() {}

// ---------------------------------------------------------------------------
// PTX helpers
// ---------------------------------------------------------------------------
__device__ __forceinline__ uint32_t smem_u32(const void* p) {
    return (uint32_t)__cvta_generic_to_shared(p);
}

__device__ __forceinline__ void cp_async16(uint32_t dst, const void* src) {
    asm volatile("cp.async.cg.shared.global [%0], [%1], 16;\n" :: "r"(dst), "l"(src));
}
__device__ __forceinline__ void cp_commit() {
    asm volatile("cp.async.commit_group;\n" ::);
}
template <int Ngroups>
__device__ __forceinline__ void cp_wait() {
    asm volatile("cp.async.wait_group %0;\n" :: "n"(Ngroups));
}

__device__ __forceinline__ void ldsm_x4(uint32_t& r0, uint32_t& r1, uint32_t& r2, uint32_t& r3,
                                        uint32_t addr) {
    asm volatile("ldmatrix.sync.aligned.m8n8.x4.shared.b16 {%0,%1,%2,%3}, [%4];\n"
                 : "=r"(r0), "=r"(r1), "=r"(r2), "=r"(r3) : "r"(addr));
}

__device__ __forceinline__ void mma16816(float& c0, float& c1, float& c2, float& c3,
                                         uint32_t a0, uint32_t a1, uint32_t a2, uint32_t a3,
                                         uint32_t b0, uint32_t b1) {
    asm volatile(
        "mma.sync.aligned.m16n8k16.row.col.f32.f16.f16.f32 "
        "{%0,%1,%2,%3}, {%4,%5,%6,%7}, {%8,%9}, {%0,%1,%2,%3};\n"
        : "+f"(c0), "+f"(c1), "+f"(c2), "+f"(c3)
        : "r"(a0), "r"(a1), "r"(a2), "r"(a3), "r"(b0), "r"(b1));
}

// ---------------------------------------------------------------------------
// GEMM: out[M,N] = scale * (XH[M,K] @ WH[N,K]^T) + bias[N]
// 8 warps (2x4 grid, 64x32 warp tiles), 3-stage cp.async, 2 CTAs/SM,
// B-fragment software pipelining across kk.
// ---------------------------------------------------------------------------
__global__ void __launch_bounds__(256, 2)
gemm_kernel(float* __restrict__ out, const float* __restrict__ scale_p,
            const float* __restrict__ bias) {
    extern __shared__ __align__(16) __half smem[];

    const int tid  = threadIdx.x;
    const int lane = tid & 31;
    const int warp = tid >> 5;
    const int wm   = warp >> 2;  // 0..1  (64-row band)
    const int wn   = warp & 3;   // 0..3  (32-col band)

    // Supertile swizzle for L2 reuse: n-groups of 16, m fastest within group.
    const int MB = M_DIM / BM;   // 64
    const int NB = N_DIM / BN;   // 86
    const int GN = 16;
    int bid   = blockIdx.x;
    int group = bid / (MB * GN);
    int rem   = bid % (MB * GN);
    int n0    = group * GN;
    int width = (NB - n0 < GN) ? (NB - n0) : GN;
    int bm    = rem / width;
    int bn    = n0 + rem % width;

    const __half* gA = g_XH + (size_t)bm * BM * K_DIM;
    const __half* gB = g_WH + (size_t)bn * BN * K_DIM;

    float acc[4][4][4];
#pragma unroll
    for (int i = 0; i < 4; i++)
#pragma unroll
        for (int j = 0; j < 4; j++)
#pragma unroll
            for (int r = 0; r < 4; r++) acc[i][j][r] = 0.0f;

    // Stage loader: A 128x64 + B 128x64 halves = 2048 16B chunks; 8 per thread.
    auto load_stage = [&](int s, int it) {
        __half* sA = smem + s * STAGE_HALVES + A_OFF;
        __half* sB = smem + s * STAGE_HALVES + B_OFF;
        const __half* a = gA + it * BK;
        const __half* b = gB + it * BK;
#pragma unroll
        for (int i = 0; i < 4; i++) {
            int c   = tid + i * 256;
            int row = c >> 3;
            int col = (c & 7) << 3;  // halves
            cp_async16(smem_u32(sA + row * SSTRIDE + col), a + (size_t)row * K_DIM + col);
        }
#pragma unroll
        for (int i = 0; i < 4; i++) {
            int c   = tid + i * 256;
            int row = c >> 3;
            int col = (c & 7) << 3;
            cp_async16(smem_u32(sB + row * SSTRIDE + col), b + (size_t)row * K_DIM + col);
        }
    };

    auto compute = [&](int s) {
        const __half* sA = smem + s * STAGE_HALVES + A_OFF;
        const __half* sB = smem + s * STAGE_HALVES + B_OFF;
        const int brow = wn * 32 + (lane & 15);
        const int bc8  = (lane >> 4) * 8;

        // Prefetch B fragments for kk=0
        uint32_t bcur[4], bnxt[4];
        ldsm_x4(bcur[0], bcur[1], bcur[2], bcur[3],
                smem_u32(sB + brow * SSTRIDE + bc8));
        ldsm_x4(bnxt[0], bnxt[1], bnxt[2], bnxt[3],
                smem_u32(sB + (brow + 16) * SSTRIDE + bc8));

#pragma unroll
        for (int kk = 0; kk < 4; kk++) {
            uint32_t a[4][4];
#pragma unroll
            for (int i = 0; i < 4; i++) {
                int row = wm * 64 + i * 16 + (lane & 15);
                int col = kk * 16 + bc8;
                ldsm_x4(a[i][0], a[i][1], a[i][2], a[i][3],
                        smem_u32(sA + row * SSTRIDE + col));
            }
            uint32_t b0[4], b1[4];
#pragma unroll
            for (int r = 0; r < 4; r++) { b0[r] = bcur[r]; b1[r] = bnxt[r]; }
            // Prefetch B fragments for kk+1 while MMAs of kk issue
            if (kk < 3) {
                int col = (kk + 1) * 16 + bc8;
                ldsm_x4(bcur[0], bcur[1], bcur[2], bcur[3],
                        smem_u32(sB + brow * SSTRIDE + col));
                ldsm_x4(bnxt[0], bnxt[1], bnxt[2], bnxt[3],
                        smem_u32(sB + (brow + 16) * SSTRIDE + col));
            }
#pragma unroll
            for (int i = 0; i < 4; i++) {
                mma16816(acc[i][0][0], acc[i][0][1], acc[i][0][2], acc[i][0][3],
                         a[i][0], a[i][1], a[i][2], a[i][3], b0[0], b0[2]);
                mma16816(acc[i][1][0], acc[i][1][1], acc[i][1][2], acc[i][1][3],
                         a[i][0], a[i][1], a[i][2], a[i][3], b0[1], b0[3]);
                mma16816(acc[i][2][0], acc[i][2][1], acc[i][2][2], acc[i][2][3],
                         a[i][0], a[i][1], a[i][2], a[i][3], b1[0], b1[2]);
                mma16816(acc[i][3][0], acc[i][3][1], acc[i][3][2], acc[i][3][3],
                         a[i][0], a[i][1], a[i][2], a[i][3], b1[1], b1[3]);
            }
        }
    };

    // Prologue: fill first 2 stages
    load_stage(0, 0);
    cp_commit();
    load_stage(1, 1);
    cp_commit();

    int slot = 0;
#pragma unroll 1
    for (int it = 0; it < NKIT; it++) {
        cp_wait<1>();       // stage 'it' loads complete (this thread)
        __syncthreads();    // complete CTA-wide; also protects slot reuse below
        int nslot = slot + 2;
        if (nslot >= STAGES) nslot -= STAGES;
        if (it + 2 < NKIT) load_stage(nslot, it + 2);
        cp_commit();        // uniform group accounting (possibly empty)
        compute(slot);
        if (++slot == STAGES) slot = 0;
    }

    // Epilogue: out = scale*acc + bias
    const float scale = __ldg(scale_p);
    const int m_base = bm * BM + wm * 64 + (lane >> 2);
    const int n_base = bn * BN + wn * 32 + (lane & 3) * 2;
#pragma unroll
    for (int i = 0; i < 4; i++) {
#pragma unroll
        for (int j = 0; j < 4; j++) {
            int m = m_base + i * 16;
            int n = n_base + j * 8;
            float2 bv = *reinterpret_cast<const float2*>(&bias[n]);
            float2 r0, r1;
            r0.x = acc[i][j][0] * scale + bv.x;
            r0.y = acc[i][j][1] * scale + bv.y;
            r1.x = acc[i][j][2] * scale + bv.x;
            r1.y = acc[i][j][3] * scale + bv.y;
            *reinterpret_cast<float2*>(&out[(size_t)m * N_DIM + n])       = r0;
            *reinterpret_cast<float2*>(&out[(size_t)(m + 8) * N_DIM + n]) = r1;
        }
    }
}

// ---------------------------------------------------------------------------
// Entry point (graph-capturable: kernel launches only)
// Launch order pads the index so ncu (-s 5 -c 1) profiles gemm_kernel.
// ---------------------------------------------------------------------------
extern "C" void kernel_launch(void* const* d_in, const int* in_sizes, int n_in,
                              void* d_out, int out_size) {
    const float* x     = (const float*)d_in[0];
    const int*   w     = (const int*)d_in[1];    // int8 promoted to int32 by harness
    const float* scale = (const float*)d_in[2];
    const float* bias  = (const float*)d_in[3];
    float*       out   = (float*)d_out;

    cudaFuncSetAttribute(gemm_kernel,
                         cudaFuncAttributeMaxDynamicSharedMemorySize, SMEM_BYTES);

    const size_t nx4 = (size_t)M_DIM * K_DIM / 4;
    cvt_x_kernel<<<(unsigned)((nx4 + 255) / 256), 256>>>(x);
    const size_t nw4 = (size_t)N_DIM * K_DIM / 4;
    cvt_w_kernel<<<(unsigned)((nw4 + 255) / 256), 256>>>(w);

    // Index padding: per-call launches = {cvt_x, cvt_w, noop, noop, noop, gemm}
    noop_kernel<<<1, 1>>>();
    noop_kernel<<<1, 1>>>();
    noop_kernel<<<1, 1>>>();

    const int grid = (M_DIM / BM) * (N_DIM / BN);  // 5504
    gemm_kernel<<<grid, 256, SMEM_BYTES>>>(out, scale, bias);
}